// round 12
// baseline (speedup 1.0000x reference)
#include <cuda_runtime.h>
#include <math.h>

#define K        8
#define D        256
#define C4       (D / 4)        // 64 16-byte cols per row
#define TILE     64             // output rows per tile
#define TROWS    (TILE + K - 1) // 71 rows staged per tile
#define SPAN     256            // rows per block (4 tiles)
#define NTILES   (SPAN / TILE)  // 4
#define THREADS  512            // 64 cols x 8 row-groups
#define RPT      8              // output rows per thread per tile
#define NEGV     (-1e9f)

#define ROWB       1024                      // bytes per row (256 f32)
#define TBYTES     (TROWS * ROWB)            // 72704
#define BUF0_OFF   0
#define BUF1_OFF   TBYTES
#define ALPHA_OFF  (2 * TBYTES)              // 145408
#define ALPHA_BYT  (SPAN * K * 8)            // 16384 (packed u64)
#define MBAR_OFF   (ALPHA_OFF + ALPHA_BYT)   // 161792
#define SMEM_TOTAL (MBAR_OFF + 16)

typedef unsigned long long u64;

__device__ __forceinline__ void fma2(u64& acc, u64 v, u64 a) {
    asm("fma.rn.f32x2 %0, %1, %2, %3;" : "=l"(acc) : "l"(v), "l"(a), "l"(acc));
}
__device__ __forceinline__ u64 pack2(float a) {
    u64 d;
    asm("mov.b64 %0, {%1, %1};" : "=l"(d) : "f"(a));
    return d;
}
__device__ __forceinline__ unsigned smem_u32(const void* p) {
    unsigned a;
    asm("{ .reg .u64 t; cvta.to.shared.u64 t, %1; cvt.u32.u64 %0, t; }"
        : "=r"(a) : "l"(p));
    return a;
}
__device__ __forceinline__ void mbar_wait(unsigned mbar, unsigned parity) {
    unsigned done;
    asm volatile(
        "{\n\t .reg .pred p;\n\t"
        "mbarrier.try_wait.parity.acquire.cta.shared::cta.b64 p, [%1], %2;\n\t"
        "selp.b32 %0, 1, 0, p;\n\t}"
        : "=r"(done) : "r"(mbar), "r"(parity) : "memory");
    if (!done) {
        asm volatile(
            "{\n\t .reg .pred P1;\n\t"
            "WL_%=:\n\t"
            "mbarrier.try_wait.parity.acquire.cta.shared::cta.b64 P1, [%0], %1, 0x989680;\n\t"
            "@P1 bra.uni WD_%=;\n\t"
            "bra.uni WL_%=;\n\t"
            "WD_%=:\n\t}"
            :: "r"(mbar), "r"(parity) : "memory");
    }
}

// valid_mask may arrive as int32 / uint8(bool) / float32; detect from word 0
// (guaranteed "true" since lengths >= N/2).
__device__ __forceinline__ bool mask_at(const void* m, int fmt, long i) {
    if (fmt == 1) return ((const unsigned char*)m)[i] != 0;
    if (fmt == 2) return ((const float*)m)[i] != 0.0f;
    return ((const int*)m)[i] != 0;
}

__global__ __launch_bounds__(THREADS)
void mixer_kernel(const float* __restrict__ x,
                  const float* __restrict__ dts,
                  const void*  __restrict__ maskp,
                  const float* __restrict__ w,
                  const float* __restrict__ beta,
                  float* __restrict__ out,
                  int N)
{
    extern __shared__ char smem[];
    float* bufs[2] = { (float*)(smem + BUF0_OFF), (float*)(smem + BUF1_OFF) };
    u64*   s_alpha2 = (u64*)(smem + ALPHA_OFF);          // [SPAN][K] packed
    const unsigned mb0 = smem_u32(smem + MBAR_OFF);
    const unsigned mb1 = mb0 + 8;

    const int  b    = blockIdx.y;
    const int  s0   = blockIdx.x * SPAN;
    const int  tid  = threadIdx.x;
    const long base = (long)b * N;

    // ---- init mbarriers ----
    if (tid == 0) {
        asm volatile("mbarrier.init.shared.b64 [%0], 1;" :: "r"(mb0) : "memory");
        asm volatile("mbarrier.init.shared.b64 [%0], 1;" :: "r"(mb1) : "memory");
    }
    __syncthreads();

    // ---- issue copy for tile 0 ----
    {
        const int rows = (N - s0 < TROWS) ? (N - s0) : TROWS;
        if (tid == 0) {
            const unsigned bytes = (unsigned)rows * ROWB;
            asm volatile("mbarrier.arrive.expect_tx.shared.b64 _, [%0], %1;"
                         :: "r"(mb0), "r"(bytes) : "memory");
            asm volatile(
                "cp.async.bulk.shared::cta.global.mbarrier::complete_tx::bytes "
                "[%0], [%1], %2, [%3];"
                :: "r"(smem_u32(bufs[0])), "l"(x + (base + s0) * (long)D),
                   "r"(bytes), "r"(mb0) : "memory");
        }
        if (rows < TROWS) {   // zero pad rows (disjoint from copy region)
            float4* pad = (float4*)(bufs[0] + rows * D);
            for (int i = tid; i < (TROWS - rows) * C4; i += THREADS)
                pad[i] = make_float4(0.f, 0.f, 0.f, 0.f);
        }
    }

    // ---- mask format detection (uniform) ----
    const unsigned int wd0 = *((const unsigned int*)maskp);
    int fmt = 0;
    if (wd0 == 0x01010101u)      fmt = 1;   // uint8 bool
    else if (wd0 == 0x3F800000u) fmt = 2;   // float32

    // ---- alphas for the whole span (overlaps copy 0) ----
    if (tid < SPAN) {
        const int  n      = s0 + tid;
        const bool valid0 = mask_at(maskp, fmt, base + n);
        const float dt0   = dts[base + n];

        float score[K];
        bool  cv[K];
        cv[0]    = valid0;
        score[0] = valid0 ? 0.0f : NEGV;
        #pragma unroll
        for (int p = 1; p < K; p++) {
            const int np = n + p;
            bool  c  = false;
            float td = 0.0f;
            if (np < N) {
                c = valid0 && mask_at(maskp, fmt, base + np);
                if (c) td = fmaxf(dts[base + np] - dt0, 0.0f);
            }
            cv[p]    = c;
            score[p] = c ? -td : NEGV;
        }

        float m = score[0];
        #pragma unroll
        for (int p = 1; p < K; p++) m = fmaxf(m, score[p]);
        float e[K], es = 0.0f;
        #pragma unroll
        for (int p = 0; p < K; p++) { e[p] = __expf(score[p] - m); es += e[p]; }
        const float inv_es = 1.0f / es;

        float wv[K];
        #pragma unroll
        for (int p = 0; p < K; p++) wv[p] = w[p];
        float wm = wv[0];
        #pragma unroll
        for (int p = 1; p < K; p++) wm = fmaxf(wm, wv[p]);
        float we[K], ws = 0.0f;
        #pragma unroll
        for (int p = 0; p < K; p++) { we[p] = __expf(wv[p] - wm); ws += we[p]; }
        const float inv_ws = 1.0f / ws;
        const float bsig   = 1.0f / (1.0f + __expf(-beta[0]));
        const float omb    = 1.0f - bsig;

        float a[K], asum = 0.0f;
        #pragma unroll
        for (int p = 0; p < K; p++) {
            a[p] = cv[p] ? (bsig * we[p] * inv_ws + omb * e[p] * inv_es) : 0.0f;
            asum += a[p];
        }
        const float inv = 1.0f / fmaxf(asum, 1e-8f);
        #pragma unroll
        for (int p = 0; p < K; p++) s_alpha2[tid * K + p] = pack2(a[p] * inv);
    }

    // ---- per-thread compute mapping ----
    const int c4  = tid & (C4 - 1);   // 0..63
    const int g   = tid >> 6;         // 0..7
    const int r0l = g * RPT;          // local row within tile

    // ================= tile pipeline =================
    #pragma unroll
    for (int t = 0; t < NTILES; t++) {
        // all threads done with buffer (t+1)&1 (used by tile t-1) and, for
        // t==0, alphas + pad written -> safe to reuse / publish
        __syncthreads();

        // ---- issue copy for tile t+1 into the other buffer ----
        if (t + 1 < NTILES) {
            const int nt0  = s0 + (t + 1) * TILE;
            const int rows = (N - nt0 < TROWS) ? (N - nt0) : TROWS;
            const unsigned mb = ((t + 1) & 1) ? mb1 : mb0;
            if (tid == 0) {
                const unsigned bytes = (unsigned)rows * ROWB;
                asm volatile("mbarrier.arrive.expect_tx.shared.b64 _, [%0], %1;"
                             :: "r"(mb), "r"(bytes) : "memory");
                asm volatile(
                    "cp.async.bulk.shared::cta.global.mbarrier::complete_tx::bytes "
                    "[%0], [%1], %2, [%3];"
                    :: "r"(smem_u32(bufs[(t + 1) & 1])),
                       "l"(x + (base + nt0) * (long)D),
                       "r"(bytes), "r"(mb) : "memory");
            }
            if (rows < TROWS) {
                float4* pad = (float4*)(bufs[(t + 1) & 1] + rows * D);
                for (int i = tid; i < (TROWS - rows) * C4; i += THREADS)
                    pad[i] = make_float4(0.f, 0.f, 0.f, 0.f);
            }
        }

        // ---- wait for tile t's copy ----
        mbar_wait((t & 1) ? mb1 : mb0, (t >> 1) & 1);

        // ---- compute tile t: sliding 8-row window over SMEM ----
        const ulonglong2* __restrict__ tr =
            (const ulonglong2*)bufs[t & 1] + r0l * C4 + c4;
        ulonglong2* __restrict__ orow =
            (ulonglong2*)out + (base + s0 + t * TILE + r0l) * (long)C4 + c4;
        const u64* __restrict__ arow = &s_alpha2[(t * TILE + r0l) * K];

        ulonglong2 win[K];
        #pragma unroll
        for (int j = 0; j < K; j++) win[j] = tr[j * C4];

        #pragma unroll
        for (int r = 0; r < RPT; r++) {
            const ulonglong2* ar = (const ulonglong2*)(arow + r * K);
            const ulonglong2 q0 = ar[0], q1 = ar[1], q2 = ar[2], q3 = ar[3];
            const u64 ap[K] = {q0.x, q0.y, q1.x, q1.y, q2.x, q2.y, q3.x, q3.y};

            u64 accx = 0ULL, accy = 0ULL;
            #pragma unroll
            for (int p = 0; p < K; p++) {
                const ulonglong2 v = win[(r + p) & (K - 1)];
                fma2(accx, v.x, ap[p]);
                fma2(accy, v.y, ap[p]);
            }
            orow[(long)r * C4] = make_ulonglong2(accx, accy);

            if (r < RPT - 1)
                win[r & (K - 1)] = tr[(r + K) * C4];
        }
    }
}

extern "C" void kernel_launch(void* const* d_in, const int* in_sizes, int n_in,
                              void* d_out, int out_size)
{
    const float* x    = (const float*)d_in[0];
    const float* dts  = (const float*)d_in[1];
    const void*  mask = d_in[2];
    const float* w    = (const float*)d_in[3];
    const float* beta = (const float*)d_in[4];

    const int BN = in_sizes[1];   // B * N
    const int B  = 8;
    const int N  = BN / B;        // 4096

    cudaFuncSetAttribute(mixer_kernel,
                         cudaFuncAttributeMaxDynamicSharedMemorySize, SMEM_TOTAL);

    dim3 grid(N / SPAN, B);       // 16 x 8 = 128 blocks, single wave
    mixer_kernel<<<grid, THREADS, SMEM_TOTAL>>>(x, dts, mask, w, beta,
                                                (float*)d_out, N);
}